// round 9
// baseline (speedup 1.0000x reference)
#include <cuda_runtime.h>
#include <cstdint>

#define NB 2
#define NH 16
#define NS 2048
#define ND 64

// Scratch (allocation-free rule: __device__ globals)
__device__ float g_Q[NB*NH*NS*ND];
__device__ float g_K[NB*NH*NS*ND];
__device__ float g_V[NB*NH*NS*ND];
__device__ unsigned g_keep[(size_t)NB*NH*NS*NS/32];   // 16MB keep bitmask

// ---------------------------------------------------------------------------
// helpers
// ---------------------------------------------------------------------------
__device__ __forceinline__ uint32_t f2tf32(float x) {
    uint32_t r;
    asm("cvt.rna.tf32.f32 %0, %1;" : "=r"(r) : "f"(x));
    return r;
}
__device__ __forceinline__ uint4 tf4(float4 v) {
    return make_uint4(f2tf32(v.x), f2tf32(v.y), f2tf32(v.z), f2tf32(v.w));
}
// m16n8k8 tf32 warp MMA, fp32 accumulate (base ISA, works on sm_103 target)
__device__ __forceinline__ void mma8(float* c, const uint32_t* a,
                                     uint32_t b0, uint32_t b1) {
    asm volatile(
        "mma.sync.aligned.m16n8k8.row.col.f32.tf32.tf32.f32 "
        "{%0,%1,%2,%3}, {%4,%5,%6,%7}, {%8,%9}, {%0,%1,%2,%3};"
        : "+f"(c[0]), "+f"(c[1]), "+f"(c[2]), "+f"(c[3])
        : "r"(a[0]), "r"(a[1]), "r"(a[2]), "r"(a[3]), "r"(b0), "r"(b1));
}

// ---------------------------------------------------------------------------
// JAX partitionable threefry2x32, key=(0,42): bits[i] = o0^o1, counter (0,i)
// Standalone kernel: at full occupancy this saturates the alu pipe (~300us
// floor); fusing it into the low-occupancy attn kernel costs ~425us (R5-R8).
// ---------------------------------------------------------------------------
__device__ __forceinline__ uint32_t rotl32(uint32_t x, int r) {
    return __funnelshift_l(x, x, r);
}
__device__ __forceinline__ void threefry2x32_42(uint32_t x0, uint32_t x1,
                                                uint32_t& o0, uint32_t& o1) {
    const uint32_t k0 = 0u, k1 = 42u, k2 = 0u ^ 42u ^ 0x1BD11BDAu;
    x0 += k0; x1 += k1;
#define TF_ROUND(r) { x0 += x1; x1 = rotl32(x1, (r)); x1 ^= x0; }
    TF_ROUND(13) TF_ROUND(15) TF_ROUND(26) TF_ROUND(6)
    x0 += k1; x1 += k2 + 1u;
    TF_ROUND(17) TF_ROUND(29) TF_ROUND(16) TF_ROUND(24)
    x0 += k2; x1 += k0 + 2u;
    TF_ROUND(13) TF_ROUND(15) TF_ROUND(26) TF_ROUND(6)
    x0 += k0; x1 += k1 + 3u;
    TF_ROUND(17) TF_ROUND(29) TF_ROUND(16) TF_ROUND(24)
    x0 += k1; x1 += k2 + 4u;
    TF_ROUND(13) TF_ROUND(15) TF_ROUND(26) TF_ROUND(6)
    x0 += k2; x1 += k0 + 5u;
#undef TF_ROUND
    o0 = x0; o1 = x1;
}
#define KEEP_THRESH 0xE6666600u   // uniform < 0.9f, exact integer reduction

__global__ void dropout_kernel() {
    uint32_t i = blockIdx.x * blockDim.x + threadIdx.x;   // [0, 2^22)
    uint32_t base = i << 5;
    uint32_t w = 0u;
#pragma unroll 8
    for (int j = 0; j < 32; j++) {
        uint32_t o0, o1;
        threefry2x32_42(0u, base + j, o0, o1);
        w |= ((o0 ^ o1) < KEEP_THRESH) ? (1u << j) : 0u;
    }
    g_keep[i] = w;
}

// ---------------------------------------------------------------------------
// QKV projection (validated in R2): Y = X @ W^T + b, output [B,H,S,D]
// One launch, grid.y selects {Q,K,V}.
// ---------------------------------------------------------------------------
__global__ void proj_kernel(const float* __restrict__ Xq,
                            const float* __restrict__ Xk,
                            const float* __restrict__ Xv,
                            const float* __restrict__ Wq_,
                            const float* __restrict__ Wk_,
                            const float* __restrict__ Wv_,
                            const float* __restrict__ bq_,
                            const float* __restrict__ bk_,
                            const float* __restrict__ bv_) {
    __shared__ __align__(16) float Xt[64][68];
    __shared__ __align__(16) float Wt[64][68];
    __shared__ float bs[64];
    int which = blockIdx.y;
    const float* X = (which == 0) ? Xq : (which == 1) ? Xk : Xv;
    const float* W = (which == 0) ? Wq_ : (which == 1) ? Wk_ : Wv_;
    const float* bias = (which == 0) ? bq_ : (which == 1) ? bk_ : bv_;
    float* Y = (which == 0) ? g_Q : (which == 1) ? g_K : g_V;

    int tid = threadIdx.x;
    if (tid < 64) bs[tid] = bias[tid];
    int r0 = blockIdx.x * 64;

#pragma unroll
    for (int r = 0; r < 4; r++) {
        int fidx = tid + r * 256;
        int row = fidx >> 4, dg = fidx & 15;
        int pg = (((row >> 2) ^ dg) << 2) + (row & 3);
        float4 w4 = reinterpret_cast<const float4*>(W)[fidx];
        Wt[4*dg+0][pg] = w4.x; Wt[4*dg+1][pg] = w4.y;
        Wt[4*dg+2][pg] = w4.z; Wt[4*dg+3][pg] = w4.w;
        float4 x4 = reinterpret_cast<const float4*>(X + (size_t)(r0 + row) * 64)[dg];
        Xt[4*dg+0][pg] = x4.x; Xt[4*dg+1][pg] = x4.y;
        Xt[4*dg+2][pg] = x4.z; Xt[4*dg+3][pg] = x4.w;
    }
    __syncthreads();

    int ty = tid >> 4, tx = tid & 15;
    float acc[4][4] = {};
#pragma unroll 8
    for (int d = 0; d < 64; d++) {
        int sw = d >> 2;
        float4 xv = *reinterpret_cast<float4*>(&Xt[d][(ty ^ sw) << 2]);
        float4 wv = *reinterpret_cast<float4*>(&Wt[d][(tx ^ sw) << 2]);
        float xa[4] = {xv.x, xv.y, xv.z, xv.w};
        float wa[4] = {wv.x, wv.y, wv.z, wv.w};
#pragma unroll
        for (int i = 0; i < 4; i++)
#pragma unroll
            for (int j = 0; j < 4; j++) acc[i][j] += xa[i] * wa[j];
    }

#pragma unroll
    for (int i = 0; i < 4; i++) {
        int r = r0 + ty * 4 + i;
        int b = r >> 15;
        int rem = r & 32767;
        int s = rem >> 4, h = rem & 15;
        float4 o;
        o.x = acc[i][0] + bs[tx*4+0];
        o.y = acc[i][1] + bs[tx*4+1];
        o.z = acc[i][2] + bs[tx*4+2];
        o.w = acc[i][3] + bs[tx*4+3];
        reinterpret_cast<float4*>(Y + ((size_t)(b*NH + h)*NS + s)*ND)[tx] = o;
    }
}

// ---------------------------------------------------------------------------
// Warp-MMA (m16n8k8 tf32) flash attention, dropout bits from g_keep bitmask.
// Block: 64 queries x head x batch, 128 threads = 4 warps (16 q-rows each).
// SMEM (uint32): Ks [64][68], Vs [64][72], Ps [4 warps][16][68]
//                (Ps doubles as Q staging before the mainloop).
// Layout identical to R5 (best known); PRNG replaced by 2x LDG.64 per tile.
// ---------------------------------------------------------------------------
#define KS_OFF 0
#define VS_OFF 4352          /* 64*68 */
#define PS_OFF 8960          /* + 64*72 */
#define SMEM_WORDS 13312     /* + 4*16*68 */

__global__ __launch_bounds__(128, 3) void attn_mma_kernel(
        const float* __restrict__ mask, float* __restrict__ out) {
    extern __shared__ __align__(16) uint32_t sm[];
    uint32_t* Ks = sm + KS_OFF;
    uint32_t* Vs = sm + VS_OFF;
    uint32_t* Ps = sm + PS_OFF;

    int tid = threadIdx.x;
    int lane = tid & 31, w = tid >> 5;       // 4 warps
    int gi = lane >> 2, ci = lane & 3;
    int qt = blockIdx.x, h = blockIdx.y, b = blockIdx.z;
    int bh = b * NH + h;
    int q0 = qt * 64;

    int row = tid >> 1, hf = tid & 1;        // staging: 64 rows x 2 halves

    // ---- stage Q (scaled 1/8, tf32) into Ps region, then build A-fragments
    {
        const float4* Qg = reinterpret_cast<const float4*>(
            g_Q + ((size_t)bh * NS + q0 + row) * ND);
        uint32_t* dst = Ps + row * 68;
#pragma unroll
        for (int j = 0; j < 8; j++) {
            float4 v = Qg[hf * 8 + j];
            v.x *= 0.125f; v.y *= 0.125f; v.z *= 0.125f; v.w *= 0.125f;
            *reinterpret_cast<uint4*>(dst + (hf * 8 + j) * 4) = tf4(v);
        }
    }
    __syncthreads();
    uint32_t qf[8][4];
    {
        const uint32_t* Qs = Ps + (w * 16) * 68;
#pragma unroll
        for (int kc = 0; kc < 8; kc++) {
            qf[kc][0] = Qs[gi * 68 + kc * 8 + ci];
            qf[kc][1] = Qs[(gi + 8) * 68 + kc * 8 + ci];
            qf[kc][2] = Qs[gi * 68 + kc * 8 + ci + 4];
            qf[kc][3] = Qs[(gi + 8) * 68 + kc * 8 + ci + 4];
        }
    }

    float oacc[8][4] = {};
    float m_lo = -3.0e38f, m_hi = -3.0e38f, l_lo = 0.f, l_hi = 0.f;

    int rlo = q0 + w * 16 + gi, rhi = rlo + 8;
    const float* mask_lo = mask + ((size_t)b * NS + rlo) * NS;
    const float* mask_hi = mask + ((size_t)b * NS + rhi) * NS;
    const unsigned* kw_lo = g_keep + (size_t)(bh * NS + rlo) * (NS / 32);
    const unsigned* kw_hi = g_keep + (size_t)(bh * NS + rhi) * (NS / 32);

    const float* Kbase = g_K + ((size_t)bh * NS + row) * ND;
    const float* Vbase = g_V + ((size_t)bh * NS + row) * ND;

    for (int kt = 0; kt < 32; kt++) {
        // ---- load K, V tile direct (convert tf32, store to smem) ----
        {
            const float4* Kg = reinterpret_cast<const float4*>(
                Kbase + (size_t)kt * 64 * ND) + hf * 8;
            float4 t[8];
#pragma unroll
            for (int j = 0; j < 8; j++) t[j] = Kg[j];
#pragma unroll
            for (int j = 0; j < 8; j++)
                *reinterpret_cast<uint4*>(Ks + row * 68 + (hf * 8 + j) * 4) = tf4(t[j]);
            const float4* Vg = reinterpret_cast<const float4*>(
                Vbase + (size_t)kt * 64 * ND) + hf * 8;
#pragma unroll
            for (int j = 0; j < 8; j++) t[j] = Vg[j];
#pragma unroll
            for (int j = 0; j < 8; j++)
                *reinterpret_cast<uint4*>(Vs + row * 72 + (hf * 8 + j) * 4) = tf4(t[j]);
        }
        __syncthreads();

        // ---- dropout keep-bits for this thread's tile columns (2x LDG.64)
        uint2 klo = *reinterpret_cast<const uint2*>(kw_lo + kt * 2);
        uint2 khi = *reinterpret_cast<const uint2*>(kw_hi + kt * 2);

        // ---- S = Q @ K^T ----
        float s[8][4] = {};
#pragma unroll
        for (int kc = 0; kc < 8; kc++) {
#pragma unroll
            for (int nt = 0; nt < 8; nt++) {
                uint32_t b0 = Ks[(nt * 8 + gi) * 68 + kc * 8 + ci];
                uint32_t b1 = Ks[(nt * 8 + gi) * 68 + kc * 8 + ci + 4];
                mma8(s[nt], qf[kc], b0, b1);
            }
        }

        // ---- mask + online softmax ----
        float mxl = -3.0e38f, mxh = -3.0e38f;
#pragma unroll
        for (int nt = 0; nt < 8; nt++) {
            float2 ml = *reinterpret_cast<const float2*>(
                mask_lo + kt * 64 + nt * 8 + 2 * ci);
            float2 mh = *reinterpret_cast<const float2*>(
                mask_hi + kt * 64 + nt * 8 + 2 * ci);
            s[nt][0] += ml.x; s[nt][1] += ml.y;
            s[nt][2] += mh.x; s[nt][3] += mh.y;
            mxl = fmaxf(mxl, fmaxf(s[nt][0], s[nt][1]));
            mxh = fmaxf(mxh, fmaxf(s[nt][2], s[nt][3]));
        }
        mxl = fmaxf(mxl, __shfl_xor_sync(0xffffffffu, mxl, 1));
        mxl = fmaxf(mxl, __shfl_xor_sync(0xffffffffu, mxl, 2));
        mxh = fmaxf(mxh, __shfl_xor_sync(0xffffffffu, mxh, 1));
        mxh = fmaxf(mxh, __shfl_xor_sync(0xffffffffu, mxh, 2));

        float nml = fmaxf(m_lo, mxl), nmh = fmaxf(m_hi, mxh);
        float scl = __expf(m_lo - nml), sch = __expf(m_hi - nmh);
        m_lo = nml; m_hi = nmh;

        float suml = 0.f, sumh = 0.f;
#pragma unroll
        for (int nt = 0; nt < 8; nt++) {
            s[nt][0] = __expf(s[nt][0] - nml);
            s[nt][1] = __expf(s[nt][1] - nml);
            s[nt][2] = __expf(s[nt][2] - nmh);
            s[nt][3] = __expf(s[nt][3] - nmh);
            suml += s[nt][0] + s[nt][1];
            sumh += s[nt][2] + s[nt][3];
        }
        suml += __shfl_xor_sync(0xffffffffu, suml, 1);
        suml += __shfl_xor_sync(0xffffffffu, suml, 2);
        sumh += __shfl_xor_sync(0xffffffffu, sumh, 1);
        sumh += __shfl_xor_sync(0xffffffffu, sumh, 2);
        l_lo = l_lo * scl + suml;
        l_hi = l_hi * sch + sumh;
#pragma unroll
        for (int nt = 0; nt < 8; nt++) {
            oacc[nt][0] *= scl; oacc[nt][1] *= scl;
            oacc[nt][2] *= sch; oacc[nt][3] *= sch;
        }

        // ---- dropout apply + P store (per-warp private region) ----
        uint32_t* Pw = Ps + w * 16 * 68;
#pragma unroll
        for (int nt = 0; nt < 8; nt++) {
            int c0 = nt * 8 + 2 * ci;
            uint32_t wl = (c0 < 32) ? klo.x : klo.y;
            uint32_t wh = (c0 < 32) ? khi.x : khi.y;
            int bit = c0 & 31;
            uint2 plo, phi;
            plo.x = ((wl >> bit) & 1u)       ? f2tf32(s[nt][0]) : 0u;
            plo.y = ((wl >> (bit + 1)) & 1u) ? f2tf32(s[nt][1]) : 0u;
            phi.x = ((wh >> bit) & 1u)       ? f2tf32(s[nt][2]) : 0u;
            phi.y = ((wh >> (bit + 1)) & 1u) ? f2tf32(s[nt][3]) : 0u;
            *reinterpret_cast<uint2*>(Pw + gi * 68 + c0) = plo;
            *reinterpret_cast<uint2*>(Pw + (gi + 8) * 68 + c0) = phi;
        }
        __syncwarp();

        // ---- O += P @ V ----
#pragma unroll
        for (int kc = 0; kc < 8; kc++) {
            uint32_t a[4];
            a[0] = Pw[gi * 68 + kc * 8 + ci];
            a[1] = Pw[(gi + 8) * 68 + kc * 8 + ci];
            a[2] = Pw[gi * 68 + kc * 8 + ci + 4];
            a[3] = Pw[(gi + 8) * 68 + kc * 8 + ci + 4];
#pragma unroll
            for (int nt = 0; nt < 8; nt++) {
                uint32_t b0 = Vs[(kc * 8 + ci) * 72 + nt * 8 + gi];
                uint32_t b1 = Vs[(kc * 8 + ci + 4) * 72 + nt * 8 + gi];
                mma8(oacc[nt], a, b0, b1);
            }
        }
        __syncthreads();
    }

    // epilogue: out = oacc / (l * 0.9)
    float invl = 1.0f / (l_lo * 0.9f);
    float invh = 1.0f / (l_hi * 0.9f);
    float* out_lo = out + ((size_t)bh * NS + rlo) * ND;
    float* out_hi = out + ((size_t)bh * NS + rhi) * ND;
#pragma unroll
    for (int nt = 0; nt < 8; nt++) {
        float2 a, c;
        a.x = oacc[nt][0] * invl; a.y = oacc[nt][1] * invl;
        c.x = oacc[nt][2] * invh; c.y = oacc[nt][3] * invh;
        *reinterpret_cast<float2*>(out_lo + nt * 8 + 2 * ci) = a;
        *reinterpret_cast<float2*>(out_hi + nt * 8 + 2 * ci) = c;
    }
}

// ---------------------------------------------------------------------------
extern "C" void kernel_launch(void* const* d_in, const int* in_sizes, int n_in,
                              void* d_out, int out_size) {
    (void)in_sizes; (void)n_in; (void)out_size;
    const float* q   = (const float*)d_in[0];
    const float* k   = (const float*)d_in[1];
    const float* v   = (const float*)d_in[2];
    const float* msk = (const float*)d_in[3];
    const float* Wq  = (const float*)d_in[4];
    const float* bq  = (const float*)d_in[5];
    const float* Wk  = (const float*)d_in[6];
    const float* bk  = (const float*)d_in[7];
    const float* Wv  = (const float*)d_in[8];
    const float* bv  = (const float*)d_in[9];
    float* out = (float*)d_out;

    const int smem_bytes = SMEM_WORDS * 4;   // 53248 B
    cudaFuncSetAttribute(attn_mma_kernel,
                         cudaFuncAttributeMaxDynamicSharedMemorySize, smem_bytes);

    dropout_kernel<<<16384, 256>>>();
    dim3 pgrid(1024, 3);
    proj_kernel<<<pgrid, 256>>>(q, k, v, Wq, Wk, Wv, bq, bk, bv);

    dim3 grid(NS / 64, NH, NB);
    attn_mma_kernel<<<grid, 128, smem_bytes>>>(msk, out);
}

// round 10
// speedup vs baseline: 1.3076x; 1.3076x over previous
#include <cuda_runtime.h>
#include <cstdint>

#define NB 2
#define NH 16
#define NS 2048
#define ND 64

// Scratch (allocation-free rule: __device__ globals)
// NOTE: g_Q/g_K/g_V hold tf32-rounded bit patterns (Q pre-scaled by 1/8),
// produced by proj_kernel, consumed raw by attn (bit-identical to R5 math).
__device__ float g_Q[NB*NH*NS*ND];
__device__ float g_K[NB*NH*NS*ND];
__device__ float g_V[NB*NH*NS*ND];

// ---------------------------------------------------------------------------
// helpers
// ---------------------------------------------------------------------------
__device__ __forceinline__ uint32_t f2tf32(float x) {
    uint32_t r;
    asm("cvt.rna.tf32.f32 %0, %1;" : "=r"(r) : "f"(x));
    return r;
}
// m16n8k8 tf32 warp MMA, fp32 accumulate (base ISA, works on sm_103 target)
__device__ __forceinline__ void mma8(float* c, const uint32_t* a,
                                     uint32_t b0, uint32_t b1) {
    asm volatile(
        "mma.sync.aligned.m16n8k8.row.col.f32.tf32.tf32.f32 "
        "{%0,%1,%2,%3}, {%4,%5,%6,%7}, {%8,%9}, {%0,%1,%2,%3};"
        : "+f"(c[0]), "+f"(c[1]), "+f"(c[2]), "+f"(c[3])
        : "r"(a[0]), "r"(a[1]), "r"(a[2]), "r"(a[3]), "r"(b0), "r"(b1));
}
__device__ __forceinline__ uint32_t smem_u32(const void* p) {
    uint32_t a;
    asm("{ .reg .u64 t; cvta.to.shared.u64 t, %1; cvt.u32.u64 %0, t; }"
        : "=r"(a) : "l"(p));
    return a;
}
__device__ __forceinline__ void cpasync16(uint32_t dst, const void* src) {
    asm volatile("cp.async.cg.shared.global [%0], [%1], 16;"
                 :: "r"(dst), "l"(src));
}
#define CP_COMMIT() asm volatile("cp.async.commit_group;" ::: "memory")
#define CP_WAIT0()  asm volatile("cp.async.wait_group 0;" ::: "memory")

// ---------------------------------------------------------------------------
// JAX partitionable threefry2x32, key=(0,42): bits[i] = o0^o1, counter (0,i)
// R5 form (best measured). Executed between cp.async issue and wait so the
// ALU work hides the GMEM->SMEM latency.
// ---------------------------------------------------------------------------
__device__ __forceinline__ uint32_t rotl32(uint32_t x, int r) {
    return __funnelshift_l(x, x, r);
}
#define KEEP_THRESH 0xE6666600u   // uniform < 0.9f, exact integer reduction

// returns bit0 = keep(e), bit1 = keep(e+1); two interleaved ciphers for ILP
__device__ __forceinline__ uint32_t keep2(uint32_t e) {
    const uint32_t k0 = 0u, k1 = 42u, k2 = 0u ^ 42u ^ 0x1BD11BDAu;
    uint32_t a0 = k0, b0 = e + k1;
    uint32_t a1 = k0, b1 = e + 1u + k1;
#define TF_R2(r) { a0 += b0; b0 = rotl32(b0, (r)) ^ a0;                        \
                   a1 += b1; b1 = rotl32(b1, (r)) ^ a1; }
    TF_R2(13) TF_R2(15) TF_R2(26) TF_R2(6)
    a0 += k1; a1 += k1; b0 += k2 + 1u; b1 += k2 + 1u;
    TF_R2(17) TF_R2(29) TF_R2(16) TF_R2(24)
    a0 += k2; a1 += k2; b0 += k0 + 2u; b1 += k0 + 2u;
    TF_R2(13) TF_R2(15) TF_R2(26) TF_R2(6)
    a0 += k0; a1 += k0; b0 += k1 + 3u; b1 += k1 + 3u;
    TF_R2(17) TF_R2(29) TF_R2(16) TF_R2(24)
    a0 += k1; a1 += k1; b0 += k2 + 4u; b1 += k2 + 4u;
    TF_R2(13) TF_R2(15) TF_R2(26) TF_R2(6)
    a0 += k2; a1 += k2; b0 += k0 + 5u; b1 += k0 + 5u;
#undef TF_R2
    uint32_t r = ((a0 ^ b0) < KEEP_THRESH) ? 1u : 0u;
    r |= ((a1 ^ b1) < KEEP_THRESH) ? 2u : 0u;
    return r;
}

// ---------------------------------------------------------------------------
// QKV projection: Y = tf32_rna(X @ W^T + b), Q additionally scaled by 1/8.
// Output [B,H,S,D]. One launch, grid.y selects {Q,K,V}.
// ---------------------------------------------------------------------------
__global__ void proj_kernel(const float* __restrict__ Xq,
                            const float* __restrict__ Xk,
                            const float* __restrict__ Xv,
                            const float* __restrict__ Wq_,
                            const float* __restrict__ Wk_,
                            const float* __restrict__ Wv_,
                            const float* __restrict__ bq_,
                            const float* __restrict__ bk_,
                            const float* __restrict__ bv_) {
    __shared__ __align__(16) float Xt[64][68];
    __shared__ __align__(16) float Wt[64][68];
    __shared__ float bs[64];
    int which = blockIdx.y;
    const float* X = (which == 0) ? Xq : (which == 1) ? Xk : Xv;
    const float* W = (which == 0) ? Wq_ : (which == 1) ? Wk_ : Wv_;
    const float* bias = (which == 0) ? bq_ : (which == 1) ? bk_ : bv_;
    float* Y = (which == 0) ? g_Q : (which == 1) ? g_K : g_V;
    float scale = (which == 0) ? 0.125f : 1.0f;

    int tid = threadIdx.x;
    if (tid < 64) bs[tid] = bias[tid];
    int r0 = blockIdx.x * 64;

#pragma unroll
    for (int r = 0; r < 4; r++) {
        int fidx = tid + r * 256;
        int row = fidx >> 4, dg = fidx & 15;
        int pg = (((row >> 2) ^ dg) << 2) + (row & 3);
        float4 w4 = reinterpret_cast<const float4*>(W)[fidx];
        Wt[4*dg+0][pg] = w4.x; Wt[4*dg+1][pg] = w4.y;
        Wt[4*dg+2][pg] = w4.z; Wt[4*dg+3][pg] = w4.w;
        float4 x4 = reinterpret_cast<const float4*>(X + (size_t)(r0 + row) * 64)[dg];
        Xt[4*dg+0][pg] = x4.x; Xt[4*dg+1][pg] = x4.y;
        Xt[4*dg+2][pg] = x4.z; Xt[4*dg+3][pg] = x4.w;
    }
    __syncthreads();

    int ty = tid >> 4, tx = tid & 15;
    float acc[4][4] = {};
#pragma unroll 8
    for (int d = 0; d < 64; d++) {
        int sw = d >> 2;
        float4 xv = *reinterpret_cast<float4*>(&Xt[d][(ty ^ sw) << 2]);
        float4 wv = *reinterpret_cast<float4*>(&Wt[d][(tx ^ sw) << 2]);
        float xa[4] = {xv.x, xv.y, xv.z, xv.w};
        float wa[4] = {wv.x, wv.y, wv.z, wv.w};
#pragma unroll
        for (int i = 0; i < 4; i++)
#pragma unroll
            for (int j = 0; j < 4; j++) acc[i][j] += xa[i] * wa[j];
    }

#pragma unroll
    for (int i = 0; i < 4; i++) {
        int r = r0 + ty * 4 + i;
        int b = r >> 15;
        int rem = r & 32767;
        int s = rem >> 4, h = rem & 15;
        uint4 o;
        o.x = f2tf32((acc[i][0] + bs[tx*4+0]) * scale);
        o.y = f2tf32((acc[i][1] + bs[tx*4+1]) * scale);
        o.z = f2tf32((acc[i][2] + bs[tx*4+2]) * scale);
        o.w = f2tf32((acc[i][3] + bs[tx*4+3]) * scale);
        reinterpret_cast<uint4*>(Y + ((size_t)(b*NH + h)*NS + s)*ND)[tx] = o;
    }
}

// ---------------------------------------------------------------------------
// Warp-MMA (m16n8k8 tf32) flash attention with FUSED threefry dropout.
// Block: 64 queries x head x batch, 128 threads = 4 warps (16 q-rows each).
// SMEM (uint32): Ks [64][68], Vs [64][72], Ps [4 warps][16][68]
//                (Ps doubles as Q staging before the mainloop).
// K/V/Q arrive pre-converted (tf32 bits) -> staging is pure cp.async; the
// per-tile PRNG executes in the cp.async latency shadow.
// ---------------------------------------------------------------------------
#define KS_OFF 0
#define VS_OFF 4352          /* 64*68 */
#define PS_OFF 8960          /* + 64*72 */
#define SMEM_WORDS 13312     /* + 4*16*68 */

__global__ __launch_bounds__(128, 3) void attn_mma_kernel(
        const float* __restrict__ mask, float* __restrict__ out) {
    extern __shared__ __align__(16) uint32_t sm[];
    uint32_t* Ks = sm + KS_OFF;
    uint32_t* Vs = sm + VS_OFF;
    uint32_t* Ps = sm + PS_OFF;
    uint32_t sb = smem_u32(sm);

    int tid = threadIdx.x;
    int lane = tid & 31, w = tid >> 5;       // 4 warps
    int gi = lane >> 2, ci = lane & 3;
    int qt = blockIdx.x, h = blockIdx.y, b = blockIdx.z;
    int bh = b * NH + h;
    int q0 = qt * 64;

    int row = tid >> 1, hf = tid & 1;        // staging: 64 rows x 2 halves

    // staging smem byte-addresses for this thread
    uint32_t ks_dst = sb + (KS_OFF + row * 68 + hf * 32) * 4;
    uint32_t vs_dst = sb + (VS_OFF + row * 72 + hf * 32) * 4;
    uint32_t ps_dst = sb + (PS_OFF + row * 68 + hf * 32) * 4;

    // ---- stage Q tile (already tf32+scaled) into Ps via cp.async ----
    {
        const float* Qg = g_Q + ((size_t)bh * NS + q0 + row) * ND + hf * 32;
#pragma unroll
        for (int j = 0; j < 8; j++)
            cpasync16(ps_dst + j * 16, Qg + j * 4);
        CP_COMMIT();
        CP_WAIT0();
    }
    __syncthreads();
    uint32_t qf[8][4];
    {
        const uint32_t* Qs = Ps + (w * 16) * 68;
#pragma unroll
        for (int kc = 0; kc < 8; kc++) {
            qf[kc][0] = Qs[gi * 68 + kc * 8 + ci];
            qf[kc][1] = Qs[(gi + 8) * 68 + kc * 8 + ci];
            qf[kc][2] = Qs[gi * 68 + kc * 8 + ci + 4];
            qf[kc][3] = Qs[(gi + 8) * 68 + kc * 8 + ci + 4];
        }
    }
    __syncthreads();   // Ps will be overwritten as P-buffer in the mainloop

    float oacc[8][4] = {};
    float m_lo = -3.0e38f, m_hi = -3.0e38f, l_lo = 0.f, l_hi = 0.f;

    int rlo = q0 + w * 16 + gi, rhi = rlo + 8;
    const float* mask_lo = mask + ((size_t)b * NS + rlo) * NS;
    const float* mask_hi = mask + ((size_t)b * NS + rhi) * NS;
    // flat dropout-element base for this thread's two rows (fits in u32: <2^27)
    uint32_t ebl = (uint32_t)(bh * NS + rlo) * NS + 2 * ci;
    uint32_t ebh = (uint32_t)(bh * NS + rhi) * NS + 2 * ci;

    const float* Kbase = g_K + ((size_t)bh * NS + row) * ND + hf * 32;
    const float* Vbase = g_V + ((size_t)bh * NS + row) * ND + hf * 32;

    for (int kt = 0; kt < 32; kt++) {
        // ---- issue K,V tile copies (GMEM -> SMEM, no registers) ----
        {
            const float* Kg = Kbase + (size_t)kt * 64 * ND;
            const float* Vg = Vbase + (size_t)kt * 64 * ND;
#pragma unroll
            for (int j = 0; j < 8; j++) {
                cpasync16(ks_dst + j * 16, Kg + j * 4);
                cpasync16(vs_dst + j * 16, Vg + j * 4);
            }
            CP_COMMIT();
        }

        // ---- fused threefry dropout, in the cp.async latency shadow ----
        uint32_t klo = 0u, khi = 0u;
        {
            uint32_t e0 = ebl + (uint32_t)kt * 64;
            uint32_t e1 = ebh + (uint32_t)kt * 64;
#pragma unroll 2
            for (int nt = 0; nt < 8; nt++) {
                klo |= keep2(e0 + nt * 8) << (2 * nt);
                khi |= keep2(e1 + nt * 8) << (2 * nt);
            }
        }

        CP_WAIT0();
        __syncthreads();

        // ---- S = Q @ K^T ----
        float s[8][4] = {};
#pragma unroll
        for (int kc = 0; kc < 8; kc++) {
#pragma unroll
            for (int nt = 0; nt < 8; nt++) {
                uint32_t b0 = Ks[(nt * 8 + gi) * 68 + kc * 8 + ci];
                uint32_t b1 = Ks[(nt * 8 + gi) * 68 + kc * 8 + ci + 4];
                mma8(s[nt], qf[kc], b0, b1);
            }
        }

        // ---- mask + online softmax ----
        float mxl = -3.0e38f, mxh = -3.0e38f;
#pragma unroll
        for (int nt = 0; nt < 8; nt++) {
            float2 ml = *reinterpret_cast<const float2*>(
                mask_lo + kt * 64 + nt * 8 + 2 * ci);
            float2 mh = *reinterpret_cast<const float2*>(
                mask_hi + kt * 64 + nt * 8 + 2 * ci);
            s[nt][0] += ml.x; s[nt][1] += ml.y;
            s[nt][2] += mh.x; s[nt][3] += mh.y;
            mxl = fmaxf(mxl, fmaxf(s[nt][0], s[nt][1]));
            mxh = fmaxf(mxh, fmaxf(s[nt][2], s[nt][3]));
        }
        mxl = fmaxf(mxl, __shfl_xor_sync(0xffffffffu, mxl, 1));
        mxl = fmaxf(mxl, __shfl_xor_sync(0xffffffffu, mxl, 2));
        mxh = fmaxf(mxh, __shfl_xor_sync(0xffffffffu, mxh, 1));
        mxh = fmaxf(mxh, __shfl_xor_sync(0xffffffffu, mxh, 2));

        float nml = fmaxf(m_lo, mxl), nmh = fmaxf(m_hi, mxh);
        float scl = __expf(m_lo - nml), sch = __expf(m_hi - nmh);
        m_lo = nml; m_hi = nmh;

        float suml = 0.f, sumh = 0.f;
#pragma unroll
        for (int nt = 0; nt < 8; nt++) {
            s[nt][0] = __expf(s[nt][0] - nml);
            s[nt][1] = __expf(s[nt][1] - nml);
            s[nt][2] = __expf(s[nt][2] - nmh);
            s[nt][3] = __expf(s[nt][3] - nmh);
            suml += s[nt][0] + s[nt][1];
            sumh += s[nt][2] + s[nt][3];
        }
        suml += __shfl_xor_sync(0xffffffffu, suml, 1);
        suml += __shfl_xor_sync(0xffffffffu, suml, 2);
        sumh += __shfl_xor_sync(0xffffffffu, sumh, 1);
        sumh += __shfl_xor_sync(0xffffffffu, sumh, 2);
        l_lo = l_lo * scl + suml;
        l_hi = l_hi * sch + sumh;
#pragma unroll
        for (int nt = 0; nt < 8; nt++) {
            oacc[nt][0] *= scl; oacc[nt][1] *= scl;
            oacc[nt][2] *= sch; oacc[nt][3] *= sch;
        }

        // ---- dropout apply + P store (per-warp private region) ----
        uint32_t* Pw = Ps + w * 16 * 68;
#pragma unroll
        for (int nt = 0; nt < 8; nt++) {
            int c0 = nt * 8 + 2 * ci;
            uint2 plo, phi;
            plo.x = ((klo >> (2 * nt)) & 1u)     ? f2tf32(s[nt][0]) : 0u;
            plo.y = ((klo >> (2 * nt + 1)) & 1u) ? f2tf32(s[nt][1]) : 0u;
            phi.x = ((khi >> (2 * nt)) & 1u)     ? f2tf32(s[nt][2]) : 0u;
            phi.y = ((khi >> (2 * nt + 1)) & 1u) ? f2tf32(s[nt][3]) : 0u;
            *reinterpret_cast<uint2*>(Pw + gi * 68 + c0) = plo;
            *reinterpret_cast<uint2*>(Pw + (gi + 8) * 68 + c0) = phi;
        }
        __syncwarp();

        // ---- O += P @ V ----
#pragma unroll
        for (int kc = 0; kc < 8; kc++) {
            uint32_t a[4];
            a[0] = Pw[gi * 68 + kc * 8 + ci];
            a[1] = Pw[(gi + 8) * 68 + kc * 8 + ci];
            a[2] = Pw[gi * 68 + kc * 8 + ci + 4];
            a[3] = Pw[(gi + 8) * 68 + kc * 8 + ci + 4];
#pragma unroll
            for (int nt = 0; nt < 8; nt++) {
                uint32_t b0 = Vs[(kc * 8 + ci) * 72 + nt * 8 + gi];
                uint32_t b1 = Vs[(kc * 8 + ci + 4) * 72 + nt * 8 + gi];
                mma8(oacc[nt], a, b0, b1);
            }
        }
        __syncthreads();
    }

    // epilogue: out = oacc / (l * 0.9)
    float invl = 1.0f / (l_lo * 0.9f);
    float invh = 1.0f / (l_hi * 0.9f);
    float* out_lo = out + ((size_t)bh * NS + rlo) * ND;
    float* out_hi = out + ((size_t)bh * NS + rhi) * ND;
#pragma unroll
    for (int nt = 0; nt < 8; nt++) {
        float2 a, c;
        a.x = oacc[nt][0] * invl; a.y = oacc[nt][1] * invl;
        c.x = oacc[nt][2] * invh; c.y = oacc[nt][3] * invh;
        *reinterpret_cast<float2*>(out_lo + nt * 8 + 2 * ci) = a;
        *reinterpret_cast<float2*>(out_hi + nt * 8 + 2 * ci) = c;
    }
}

// ---------------------------------------------------------------------------
extern "C" void kernel_launch(void* const* d_in, const int* in_sizes, int n_in,
                              void* d_out, int out_size) {
    (void)in_sizes; (void)n_in; (void)out_size;
    const float* q   = (const float*)d_in[0];
    const float* k   = (const float*)d_in[1];
    const float* v   = (const float*)d_in[2];
    const float* msk = (const float*)d_in[3];
    const float* Wq  = (const float*)d_in[4];
    const float* bq  = (const float*)d_in[5];
    const float* Wk  = (const float*)d_in[6];
    const float* bk  = (const float*)d_in[7];
    const float* Wv  = (const float*)d_in[8];
    const float* bv  = (const float*)d_in[9];
    float* out = (float*)d_out;

    const int smem_bytes = SMEM_WORDS * 4;   // 53248 B
    cudaFuncSetAttribute(attn_mma_kernel,
                         cudaFuncAttributeMaxDynamicSharedMemorySize, smem_bytes);

    dim3 pgrid(1024, 3);
    proj_kernel<<<pgrid, 256>>>(q, k, v, Wq, Wk, Wv, bq, bk, bv);

    dim3 grid(NS / 64, NH, NB);
    attn_mma_kernel<<<grid, 128, smem_bytes>>>(msk, out);
}